// round 3
// baseline (speedup 1.0000x reference)
#include <cuda_runtime.h>

#define NN 100000
#define NE 1600000
#define DIN 128
#define DH  64
#define NB_SCAN 25   // ceil(NN / 4096)

// Scratch (static device globals — no allocation allowed)
__device__ __align__(16) float g_y[NN * DH];    // x @ w1a
__device__ __align__(16) float g_t1[NN * DH];   // relu(y + agg1 + b1a)
__device__ __align__(16) float g_z[NN * DH];    // h1 @ w2a
__device__ __align__(16) float g_sums[DH];      // pooled sums
__device__ int g_deg[NN];
__device__ int g_rowptr[NN + 1];
__device__ int g_cursor[NN];
__device__ int g_csr_src[NE];
__device__ int g_bsum[NB_SCAN];
__device__ int g_boff[NB_SCAN];

// ---------------------------------------------------------------------------
// CSR build: zero -> histogram -> block scan -> top scan -> add -> fill
// ---------------------------------------------------------------------------
__global__ void zero0_kernel() {
    int i = blockIdx.x * blockDim.x + threadIdx.x;
    if (i < NN) g_deg[i] = 0;
    if (i < DH) g_sums[i] = 0.f;
}

__global__ void hist_kernel(const int* __restrict__ ei) {
    int e = blockIdx.x * blockDim.x + threadIdx.x;
    if (e >= NE) return;
    unsigned dst = (unsigned)ei[NE + e];
    if (dst < NN) atomicAdd(&g_deg[dst], 1);
}

__global__ void scan_blocks_kernel() {
    __shared__ int warp_sums[32];
    const int tid = threadIdx.x, blk = blockIdx.x;
    const int base = blk * 4096 + tid * 4;
    int v0 = (base + 0 < NN) ? g_deg[base + 0] : 0;
    int v1 = (base + 1 < NN) ? g_deg[base + 1] : 0;
    int v2 = (base + 2 < NN) ? g_deg[base + 2] : 0;
    int v3 = (base + 3 < NN) ? g_deg[base + 3] : 0;
    int s = v0 + v1 + v2 + v3;
    const int lane = tid & 31, wid = tid >> 5;
    int inc = s;
    #pragma unroll
    for (int o = 1; o < 32; o <<= 1) {
        int n = __shfl_up_sync(0xffffffffu, inc, o);
        if (lane >= o) inc += n;
    }
    if (lane == 31) warp_sums[wid] = inc;
    __syncthreads();
    if (wid == 0) {
        int ws = warp_sums[lane];
        int winc = ws;
        #pragma unroll
        for (int o = 1; o < 32; o <<= 1) {
            int n = __shfl_up_sync(0xffffffffu, winc, o);
            if (lane >= o) winc += n;
        }
        warp_sums[lane] = winc - ws;   // exclusive
        if (lane == 31) g_bsum[blk] = winc;  // block total
    }
    __syncthreads();
    int excl = inc - s + warp_sums[wid];
    if (base + 0 < NN) g_rowptr[base + 0] = excl;           excl += v0;
    if (base + 1 < NN) g_rowptr[base + 1] = excl;           excl += v1;
    if (base + 2 < NN) g_rowptr[base + 2] = excl;           excl += v2;
    if (base + 3 < NN) g_rowptr[base + 3] = excl;
}

__global__ void scan_top_kernel() {
    const int lane = threadIdx.x;
    int s = (lane < NB_SCAN) ? g_bsum[lane] : 0;
    int inc = s;
    #pragma unroll
    for (int o = 1; o < 32; o <<= 1) {
        int n = __shfl_up_sync(0xffffffffu, inc, o);
        if (lane >= o) inc += n;
    }
    if (lane < NB_SCAN) g_boff[lane] = inc - s;
    if (lane == 31) g_rowptr[NN] = inc;   // total edge count landing in-range
}

__global__ void scan_add_kernel() {
    int i = blockIdx.x * blockDim.x + threadIdx.x;
    if (i >= NN) return;
    int r = g_rowptr[i] + g_boff[i >> 12];
    g_rowptr[i] = r;
    g_cursor[i] = r;
}

__global__ void fill_kernel(const int* __restrict__ ei) {
    int e = blockIdx.x * blockDim.x + threadIdx.x;
    if (e >= NE) return;
    unsigned src = (unsigned)ei[e];
    unsigned dst = (unsigned)ei[NE + e];
    if (src >= NN || dst >= NN) return;
    int pos = atomicAdd(&g_cursor[dst], 1);
    g_csr_src[pos] = (int)src;
}

// ---------------------------------------------------------------------------
// GEMM1: y = x @ w1a      [100000,128] x [128,64]
// 64 nodes/block, 256 threads; thread = 2 nodes x 8 outs, k chunked by 4.
// ---------------------------------------------------------------------------
__global__ void gemm1_kernel(const float* __restrict__ x,
                             const float* __restrict__ w1a) {
    extern __shared__ float sm[];
    float* ws = sm;                 // 128*64
    float* xs = sm + DIN * DH;      // 64 rows, stride 132 floats (33 float4)

    const int t = threadIdx.x;
    const int nb = blockIdx.x * 64;

    #pragma unroll
    for (int i = 0; i < (DIN * DH) / 256; i++)
        ws[i * 256 + t] = w1a[i * 256 + t];

    #pragma unroll
    for (int i = 0; i < 8; i++) {
        int flat = i * 256 + t;     // float4 index
        int node = flat >> 5;
        int f4   = flat & 31;
        float4 v = make_float4(0.f, 0.f, 0.f, 0.f);
        if (nb + node < NN)
            v = ((const float4*)x)[(size_t)(nb + node) * 32 + f4];
        *(float4*)&xs[node * 132 + f4 * 4] = v;
    }
    __syncthreads();

    const int og = t & 7;     // outs og*8 .. og*8+7
    const int ng = t >> 3;    // nodes ng*2, ng*2+1
    const float4* ws4 = (const float4*)ws;
    const float4* xs4 = (const float4*)xs;

    float acc[2][8] = {};
    #pragma unroll 2
    for (int k4 = 0; k4 < DIN; k4 += 4) {
        float4 xa = xs4[(ng * 2 + 0) * 33 + (k4 >> 2)];
        float4 xb = xs4[(ng * 2 + 1) * 33 + (k4 >> 2)];
        float xav[4] = {xa.x, xa.y, xa.z, xa.w};
        float xbv[4] = {xb.x, xb.y, xb.z, xb.w};
        #pragma unroll
        for (int kk = 0; kk < 4; kk++) {
            float4 wA = ws4[(k4 + kk) * 16 + og * 2 + 0];
            float4 wB = ws4[(k4 + kk) * 16 + og * 2 + 1];
            acc[0][0] += xav[kk] * wA.x;  acc[0][1] += xav[kk] * wA.y;
            acc[0][2] += xav[kk] * wA.z;  acc[0][3] += xav[kk] * wA.w;
            acc[0][4] += xav[kk] * wB.x;  acc[0][5] += xav[kk] * wB.y;
            acc[0][6] += xav[kk] * wB.z;  acc[0][7] += xav[kk] * wB.w;
            acc[1][0] += xbv[kk] * wA.x;  acc[1][1] += xbv[kk] * wA.y;
            acc[1][2] += xbv[kk] * wA.z;  acc[1][3] += xbv[kk] * wA.w;
            acc[1][4] += xbv[kk] * wB.x;  acc[1][5] += xbv[kk] * wB.y;
            acc[1][6] += xbv[kk] * wB.z;  acc[1][7] += xbv[kk] * wB.w;
        }
    }
    #pragma unroll
    for (int j = 0; j < 2; j++) {
        int node = nb + ng * 2 + j;
        if (node < NN) {
            ((float4*)g_y)[(size_t)node * 16 + og * 2 + 0] =
                make_float4(acc[j][0], acc[j][1], acc[j][2], acc[j][3]);
            ((float4*)g_y)[(size_t)node * 16 + og * 2 + 1] =
                make_float4(acc[j][4], acc[j][5], acc[j][6], acc[j][7]);
        }
    }
}

// ---------------------------------------------------------------------------
// Gather1: t1[i] = relu(y[i] + sum_{j->i} y[j] + b1a)
// 16 nodes/block, 16 threads (float4 channels) per node.
// ---------------------------------------------------------------------------
__global__ void gather1_kernel(const float* __restrict__ b1a) {
    const int t = threadIdx.x;
    const int node = blockIdx.x * 16 + (t >> 4);
    const int c = t & 15;
    if (node >= NN) return;
    const int beg = g_rowptr[node];
    const int end = g_rowptr[node + 1];
    float4 acc = ((const float4*)g_y)[(size_t)node * 16 + c];
    float4 bb = ((const float4*)b1a)[c];
    acc.x += bb.x; acc.y += bb.y; acc.z += bb.z; acc.w += bb.w;
    for (int e = beg; e < end; e++) {
        int s = g_csr_src[e];
        float4 v = ((const float4*)g_y)[(size_t)s * 16 + c];
        acc.x += v.x; acc.y += v.y; acc.z += v.z; acc.w += v.w;
    }
    acc.x = fmaxf(acc.x, 0.f); acc.y = fmaxf(acc.y, 0.f);
    acc.z = fmaxf(acc.z, 0.f); acc.w = fmaxf(acc.w, 0.f);
    ((float4*)g_t1)[(size_t)node * 16 + c] = acc;
}

// ---------------------------------------------------------------------------
// Fused middle:
//   h1 = relu(t1 @ w1b + b1b)   (smem)
//   z  = h1 @ w2a               (-> global; b2a applied in gather2)
// 64 nodes/block, 256 threads; thread = 2 nodes x 8 outs.
// ---------------------------------------------------------------------------
__global__ void fused_mid_kernel(const float* __restrict__ w1b,
                                 const float* __restrict__ b1b,
                                 const float* __restrict__ w2a) {
    extern __shared__ float sm[];
    float* ws1 = sm;                   // 64*64
    float* ws2 = sm + 4096;            // 64*64
    float* t1s = sm + 8192;            // 64 x stride 68
    float* h1s = t1s + 64 * 68;        // 64 x stride 68
    __shared__ __align__(16) float b1bs[64];

    const int t = threadIdx.x;
    const int nb = blockIdx.x * 64;

    #pragma unroll
    for (int i = 0; i < 16; i++) {
        ws1[i * 256 + t] = w1b[i * 256 + t];
        ws2[i * 256 + t] = w2a[i * 256 + t];
    }
    if (t < 64) b1bs[t] = b1b[t];

    #pragma unroll
    for (int i = 0; i < 4; i++) {
        int flat = i * 256 + t;   // float4 index in 64x16
        int node = flat >> 4;
        int f4   = flat & 15;
        float4 v = make_float4(0.f, 0.f, 0.f, 0.f);
        if (nb + node < NN)
            v = ((const float4*)g_t1)[(size_t)(nb + node) * 16 + f4];
        *(float4*)&t1s[node * 68 + f4 * 4] = v;
    }
    __syncthreads();

    const int og = t & 7;
    const int ng = t >> 3;
    const float4* ws1_4 = (const float4*)ws1;
    const float4* ws2_4 = (const float4*)ws2;
    const float4* t1s4 = (const float4*)t1s;
    const float4* h1s4 = (const float4*)h1s;

    // stage 2: h1 = relu(t1 @ w1b + b1b)
    {
        float acc[2][8] = {};
        #pragma unroll 2
        for (int k4 = 0; k4 < DH; k4 += 4) {
            float4 xa = t1s4[(ng * 2 + 0) * 17 + (k4 >> 2)];
            float4 xb = t1s4[(ng * 2 + 1) * 17 + (k4 >> 2)];
            float xav[4] = {xa.x, xa.y, xa.z, xa.w};
            float xbv[4] = {xb.x, xb.y, xb.z, xb.w};
            #pragma unroll
            for (int kk = 0; kk < 4; kk++) {
                float4 wA = ws1_4[(k4 + kk) * 16 + og * 2 + 0];
                float4 wB = ws1_4[(k4 + kk) * 16 + og * 2 + 1];
                acc[0][0] += xav[kk] * wA.x;  acc[0][1] += xav[kk] * wA.y;
                acc[0][2] += xav[kk] * wA.z;  acc[0][3] += xav[kk] * wA.w;
                acc[0][4] += xav[kk] * wB.x;  acc[0][5] += xav[kk] * wB.y;
                acc[0][6] += xav[kk] * wB.z;  acc[0][7] += xav[kk] * wB.w;
                acc[1][0] += xbv[kk] * wA.x;  acc[1][1] += xbv[kk] * wA.y;
                acc[1][2] += xbv[kk] * wA.z;  acc[1][3] += xbv[kk] * wA.w;
                acc[1][4] += xbv[kk] * wB.x;  acc[1][5] += xbv[kk] * wB.y;
                acc[1][6] += xbv[kk] * wB.z;  acc[1][7] += xbv[kk] * wB.w;
            }
        }
        float4 bA = *(const float4*)&b1bs[og * 8 + 0];
        float4 bB = *(const float4*)&b1bs[og * 8 + 4];
        #pragma unroll
        for (int j = 0; j < 2; j++) {
            float4 h0, h1;
            h0.x = fmaxf(acc[j][0] + bA.x, 0.f);
            h0.y = fmaxf(acc[j][1] + bA.y, 0.f);
            h0.z = fmaxf(acc[j][2] + bA.z, 0.f);
            h0.w = fmaxf(acc[j][3] + bA.w, 0.f);
            h1.x = fmaxf(acc[j][4] + bB.x, 0.f);
            h1.y = fmaxf(acc[j][5] + bB.y, 0.f);
            h1.z = fmaxf(acc[j][6] + bB.z, 0.f);
            h1.w = fmaxf(acc[j][7] + bB.w, 0.f);
            *(float4*)&h1s[(ng * 2 + j) * 68 + og * 8 + 0] = h0;
            *(float4*)&h1s[(ng * 2 + j) * 68 + og * 8 + 4] = h1;
        }
    }
    __syncthreads();

    // stage 3: z = h1 @ w2a
    {
        float acc[2][8] = {};
        #pragma unroll 2
        for (int k4 = 0; k4 < DH; k4 += 4) {
            float4 xa = h1s4[(ng * 2 + 0) * 17 + (k4 >> 2)];
            float4 xb = h1s4[(ng * 2 + 1) * 17 + (k4 >> 2)];
            float xav[4] = {xa.x, xa.y, xa.z, xa.w};
            float xbv[4] = {xb.x, xb.y, xb.z, xb.w};
            #pragma unroll
            for (int kk = 0; kk < 4; kk++) {
                float4 wA = ws2_4[(k4 + kk) * 16 + og * 2 + 0];
                float4 wB = ws2_4[(k4 + kk) * 16 + og * 2 + 1];
                acc[0][0] += xav[kk] * wA.x;  acc[0][1] += xav[kk] * wA.y;
                acc[0][2] += xav[kk] * wA.z;  acc[0][3] += xav[kk] * wA.w;
                acc[0][4] += xav[kk] * wB.x;  acc[0][5] += xav[kk] * wB.y;
                acc[0][6] += xav[kk] * wB.z;  acc[0][7] += xav[kk] * wB.w;
                acc[1][0] += xbv[kk] * wA.x;  acc[1][1] += xbv[kk] * wA.y;
                acc[1][2] += xbv[kk] * wA.z;  acc[1][3] += xbv[kk] * wA.w;
                acc[1][4] += xbv[kk] * wB.x;  acc[1][5] += xbv[kk] * wB.y;
                acc[1][6] += xbv[kk] * wB.z;  acc[1][7] += xbv[kk] * wB.w;
            }
        }
        #pragma unroll
        for (int j = 0; j < 2; j++) {
            int node = nb + ng * 2 + j;
            if (node < NN) {
                ((float4*)g_z)[(size_t)node * 16 + og * 2 + 0] =
                    make_float4(acc[j][0], acc[j][1], acc[j][2], acc[j][3]);
                ((float4*)g_z)[(size_t)node * 16 + og * 2 + 1] =
                    make_float4(acc[j][4], acc[j][5], acc[j][6], acc[j][7]);
            }
        }
    }
}

// ---------------------------------------------------------------------------
// Gather2 + pool: sums += relu(z[i] + sum_{j->i} z[j] + b2a) over all i
// ---------------------------------------------------------------------------
__global__ void gather2_kernel(const float* __restrict__ b2a) {
    __shared__ __align__(16) float4 sd[256];
    const int t = threadIdx.x;
    const int node = blockIdx.x * 16 + (t >> 4);
    const int c = t & 15;
    float4 acc = make_float4(0.f, 0.f, 0.f, 0.f);
    if (node < NN) {
        const int beg = g_rowptr[node];
        const int end = g_rowptr[node + 1];
        acc = ((const float4*)g_z)[(size_t)node * 16 + c];
        float4 bb = ((const float4*)b2a)[c];
        acc.x += bb.x; acc.y += bb.y; acc.z += bb.z; acc.w += bb.w;
        for (int e = beg; e < end; e++) {
            int s = g_csr_src[e];
            float4 v = ((const float4*)g_z)[(size_t)s * 16 + c];
            acc.x += v.x; acc.y += v.y; acc.z += v.z; acc.w += v.w;
        }
        acc.x = fmaxf(acc.x, 0.f); acc.y = fmaxf(acc.y, 0.f);
        acc.z = fmaxf(acc.z, 0.f); acc.w = fmaxf(acc.w, 0.f);
    }
    sd[t] = acc;
    __syncthreads();
    if (t < 16) {
        float4 s = sd[t];
        #pragma unroll
        for (int i = 1; i < 16; i++) {
            float4 v = sd[t + i * 16];
            s.x += v.x; s.y += v.y; s.z += v.z; s.w += v.w;
        }
        atomicAdd(&g_sums[t * 4 + 0], s.x);
        atomicAdd(&g_sums[t * 4 + 1], s.y);
        atomicAdd(&g_sums[t * 4 + 2], s.z);
        atomicAdd(&g_sums[t * 4 + 3], s.w);
    }
}

// ---------------------------------------------------------------------------
// Final: out = sums @ w2b + NN * b2b    (1 x 64)
// ---------------------------------------------------------------------------
__global__ void final_kernel(const float* __restrict__ w2b,
                             const float* __restrict__ b2b,
                             float* __restrict__ out) {
    int o = threadIdx.x;
    float acc = (float)NN * b2b[o];
    #pragma unroll 8
    for (int j = 0; j < 64; j++)
        acc += g_sums[j] * w2b[j * 64 + o];
    out[o] = acc;
}

// ---------------------------------------------------------------------------
extern "C" void kernel_launch(void* const* d_in, const int* in_sizes, int n_in,
                              void* d_out, int out_size) {
    const float* x   = (const float*)d_in[0];
    const int*   ei  = (const int*)d_in[1];   // int32
    const float* w1a = (const float*)d_in[2];
    const float* b1a = (const float*)d_in[3];
    const float* w1b = (const float*)d_in[4];
    const float* b1b = (const float*)d_in[5];
    const float* w2a = (const float*)d_in[6];
    const float* b2a = (const float*)d_in[7];
    const float* w2b = (const float*)d_in[8];
    const float* b2b = (const float*)d_in[9];
    float*       out = (float*)d_out;

    (void)in_sizes; (void)n_in; (void)out_size;

    const int SMEM_G1  = (DIN * DH + 64 * 132) * 4;           // 66560 B
    const int SMEM_MID = (2 * DH * DH + 2 * 64 * 68) * 4;     // 67584 B
    cudaFuncSetAttribute(gemm1_kernel,
                         cudaFuncAttributeMaxDynamicSharedMemorySize, SMEM_G1);
    cudaFuncSetAttribute(fused_mid_kernel,
                         cudaFuncAttributeMaxDynamicSharedMemorySize, SMEM_MID);

    // CSR build
    zero0_kernel<<<(NN + 255) / 256, 256>>>();
    hist_kernel<<<(NE + 255) / 256, 256>>>(ei);
    scan_blocks_kernel<<<NB_SCAN, 1024>>>();
    scan_top_kernel<<<1, 32>>>();
    scan_add_kernel<<<(NN + 255) / 256, 256>>>();
    fill_kernel<<<(NE + 255) / 256, 256>>>(ei);

    // Compute
    gemm1_kernel<<<(NN + 63) / 64, 256, SMEM_G1>>>(x, w1a);
    gather1_kernel<<<(NN + 15) / 16, 256>>>(b1a);
    fused_mid_kernel<<<(NN + 63) / 64, 256, SMEM_MID>>>(w1b, b1b, w2a);
    gather2_kernel<<<(NN + 15) / 16, 256>>>(b2a);
    final_kernel<<<1, 64>>>(w2b, b2b, out);
}

// round 4
// speedup vs baseline: 1.0156x; 1.0156x over previous
#include <cuda_runtime.h>

#define NN 100000
#define NE 1600000
#define DIN 128
#define DH  64

// Scratch (static device globals — no allocation allowed)
__device__ __align__(16) float g_y[NN * DH];     // x @ w1a (clean scatter source)
__device__ __align__(16) float g_agg1[NN * DH];  // y + b1a + sum_{j->i} y[j]
__device__ __align__(16) float g_z[NN * DH];     // h1 @ w2a (clean scatter source)
__device__ __align__(16) float g_agg2[NN * DH];  // z + b2a + sum_{j->i} z[j]
__device__ __align__(16) float g_sums[DH];       // pooled sums

// ---------------------------------------------------------------------------
// GEMM1: y = x @ w1a      [100000,128] x [128,64]
// Writes g_y = y  AND  g_agg1 = y + b1a  (scatter accumulator pre-seeded).
// 64 nodes/block, 256 threads; thread = 2 nodes x 8 outs.
// ---------------------------------------------------------------------------
__global__ void gemm1_kernel(const float* __restrict__ x,
                             const float* __restrict__ w1a,
                             const float* __restrict__ b1a) {
    extern __shared__ float sm[];
    float* ws = sm;                 // 128*64
    float* xs = sm + DIN * DH;      // 64 rows, stride 132 floats (33 float4)

    const int t = threadIdx.x;
    const int nb = blockIdx.x * 64;

    if (blockIdx.x == 0 && t < DH) g_sums[t] = 0.f;

    #pragma unroll
    for (int i = 0; i < (DIN * DH) / 256; i++)
        ws[i * 256 + t] = w1a[i * 256 + t];

    #pragma unroll
    for (int i = 0; i < 8; i++) {
        int flat = i * 256 + t;     // float4 index
        int node = flat >> 5;
        int f4   = flat & 31;
        float4 v = make_float4(0.f, 0.f, 0.f, 0.f);
        if (nb + node < NN)
            v = ((const float4*)x)[(size_t)(nb + node) * 32 + f4];
        *(float4*)&xs[node * 132 + f4 * 4] = v;
    }
    __syncthreads();

    const int og = t & 7;     // outs og*8 .. og*8+7
    const int ng = t >> 3;    // nodes ng*2, ng*2+1
    const float4* ws4 = (const float4*)ws;
    const float4* xs4 = (const float4*)xs;

    float acc[2][8] = {};
    #pragma unroll 2
    for (int k4 = 0; k4 < DIN; k4 += 4) {
        float4 xa = xs4[(ng * 2 + 0) * 33 + (k4 >> 2)];
        float4 xb = xs4[(ng * 2 + 1) * 33 + (k4 >> 2)];
        float xav[4] = {xa.x, xa.y, xa.z, xa.w};
        float xbv[4] = {xb.x, xb.y, xb.z, xb.w};
        #pragma unroll
        for (int kk = 0; kk < 4; kk++) {
            float4 wA = ws4[(k4 + kk) * 16 + og * 2 + 0];
            float4 wB = ws4[(k4 + kk) * 16 + og * 2 + 1];
            acc[0][0] += xav[kk] * wA.x;  acc[0][1] += xav[kk] * wA.y;
            acc[0][2] += xav[kk] * wA.z;  acc[0][3] += xav[kk] * wA.w;
            acc[0][4] += xav[kk] * wB.x;  acc[0][5] += xav[kk] * wB.y;
            acc[0][6] += xav[kk] * wB.z;  acc[0][7] += xav[kk] * wB.w;
            acc[1][0] += xbv[kk] * wA.x;  acc[1][1] += xbv[kk] * wA.y;
            acc[1][2] += xbv[kk] * wA.z;  acc[1][3] += xbv[kk] * wA.w;
            acc[1][4] += xbv[kk] * wB.x;  acc[1][5] += xbv[kk] * wB.y;
            acc[1][6] += xbv[kk] * wB.z;  acc[1][7] += xbv[kk] * wB.w;
        }
    }
    float4 bA = ((const float4*)b1a)[og * 2 + 0];
    float4 bB = ((const float4*)b1a)[og * 2 + 1];
    #pragma unroll
    for (int j = 0; j < 2; j++) {
        int node = nb + ng * 2 + j;
        if (node < NN) {
            float4 y0 = make_float4(acc[j][0], acc[j][1], acc[j][2], acc[j][3]);
            float4 y1 = make_float4(acc[j][4], acc[j][5], acc[j][6], acc[j][7]);
            size_t g = (size_t)node * 16 + og * 2;
            ((float4*)g_y)[g + 0] = y0;
            ((float4*)g_y)[g + 1] = y1;
            ((float4*)g_agg1)[g + 0] =
                make_float4(y0.x + bA.x, y0.y + bA.y, y0.z + bA.z, y0.w + bA.w);
            ((float4*)g_agg1)[g + 1] =
                make_float4(y1.x + bB.x, y1.y + bB.y, y1.z + bB.z, y1.w + bB.w);
        }
    }
}

// ---------------------------------------------------------------------------
// Edge scatter: agg[dst] += vec[src], 16 threads/edge, red.global.add.v4.f32
// edge_index is int32.
// ---------------------------------------------------------------------------
__device__ __forceinline__ void scatter_body(const float* __restrict__ vec,
                                             float* __restrict__ agg,
                                             const int* __restrict__ ei) {
    long long tid = (long long)blockIdx.x * blockDim.x + threadIdx.x;
    if (tid >= (long long)NE * 16) return;
    int e = (int)(tid >> 4);
    int c = (int)(tid & 15);
    unsigned src = (unsigned)ei[e];
    unsigned dst = (unsigned)ei[NE + e];
    if (src >= NN || dst >= NN) return;
    float4 v = ((const float4*)vec)[(size_t)src * 16 + c];
    float* p = agg + ((size_t)dst * 64 + c * 4);
    asm volatile("red.global.add.v4.f32 [%0], {%1,%2,%3,%4};"
                 :: "l"(p), "f"(v.x), "f"(v.y), "f"(v.z), "f"(v.w)
                 : "memory");
}

__global__ void scatter1_kernel(const int* __restrict__ ei) {
    scatter_body(g_y, g_agg1, ei);
}
__global__ void scatter2_kernel(const int* __restrict__ ei) {
    scatter_body(g_z, g_agg2, ei);
}

// ---------------------------------------------------------------------------
// Fused middle:
//   t1 = relu(agg1)                (b1a already folded in)
//   h1 = relu(t1 @ w1b + b1b)      (smem)
//   z  = h1 @ w2a                  -> g_z  AND  g_agg2 = z + b2a
// 64 nodes/block, 256 threads; thread = 2 nodes x 8 outs.
// ---------------------------------------------------------------------------
__global__ void fused_mid_kernel(const float* __restrict__ w1b,
                                 const float* __restrict__ b1b,
                                 const float* __restrict__ w2a,
                                 const float* __restrict__ b2a) {
    extern __shared__ float sm[];
    float* ws1 = sm;                   // 64*64
    float* ws2 = sm + 4096;            // 64*64
    float* t1s = sm + 8192;            // 64 x stride 68
    float* h1s = t1s + 64 * 68;        // 64 x stride 68
    __shared__ __align__(16) float b1bs[64];

    const int t = threadIdx.x;
    const int nb = blockIdx.x * 64;

    #pragma unroll
    for (int i = 0; i < 16; i++) {
        ws1[i * 256 + t] = w1b[i * 256 + t];
        ws2[i * 256 + t] = w2a[i * 256 + t];
    }
    if (t < 64) b1bs[t] = b1b[t];

    // stage 1: t1 = relu(agg1)
    #pragma unroll
    for (int i = 0; i < 4; i++) {
        int flat = i * 256 + t;   // float4 index in 64x16
        int node = flat >> 4;
        int f4   = flat & 15;
        float4 v = make_float4(0.f, 0.f, 0.f, 0.f);
        if (nb + node < NN) {
            float4 a = ((const float4*)g_agg1)[(size_t)(nb + node) * 16 + f4];
            v.x = fmaxf(a.x, 0.f); v.y = fmaxf(a.y, 0.f);
            v.z = fmaxf(a.z, 0.f); v.w = fmaxf(a.w, 0.f);
        }
        *(float4*)&t1s[node * 68 + f4 * 4] = v;
    }
    __syncthreads();

    const int og = t & 7;
    const int ng = t >> 3;
    const float4* ws1_4 = (const float4*)ws1;
    const float4* ws2_4 = (const float4*)ws2;
    const float4* t1s4 = (const float4*)t1s;
    const float4* h1s4 = (const float4*)h1s;

    // stage 2: h1 = relu(t1 @ w1b + b1b)
    {
        float acc[2][8] = {};
        #pragma unroll 2
        for (int k4 = 0; k4 < DH; k4 += 4) {
            float4 xa = t1s4[(ng * 2 + 0) * 17 + (k4 >> 2)];
            float4 xb = t1s4[(ng * 2 + 1) * 17 + (k4 >> 2)];
            float xav[4] = {xa.x, xa.y, xa.z, xa.w};
            float xbv[4] = {xb.x, xb.y, xb.z, xb.w};
            #pragma unroll
            for (int kk = 0; kk < 4; kk++) {
                float4 wA = ws1_4[(k4 + kk) * 16 + og * 2 + 0];
                float4 wB = ws1_4[(k4 + kk) * 16 + og * 2 + 1];
                acc[0][0] += xav[kk] * wA.x;  acc[0][1] += xav[kk] * wA.y;
                acc[0][2] += xav[kk] * wA.z;  acc[0][3] += xav[kk] * wA.w;
                acc[0][4] += xav[kk] * wB.x;  acc[0][5] += xav[kk] * wB.y;
                acc[0][6] += xav[kk] * wB.z;  acc[0][7] += xav[kk] * wB.w;
                acc[1][0] += xbv[kk] * wA.x;  acc[1][1] += xbv[kk] * wA.y;
                acc[1][2] += xbv[kk] * wA.z;  acc[1][3] += xbv[kk] * wA.w;
                acc[1][4] += xbv[kk] * wB.x;  acc[1][5] += xbv[kk] * wB.y;
                acc[1][6] += xbv[kk] * wB.z;  acc[1][7] += xbv[kk] * wB.w;
            }
        }
        float4 bA = *(const float4*)&b1bs[og * 8 + 0];
        float4 bB = *(const float4*)&b1bs[og * 8 + 4];
        #pragma unroll
        for (int j = 0; j < 2; j++) {
            float4 h0, h1;
            h0.x = fmaxf(acc[j][0] + bA.x, 0.f);
            h0.y = fmaxf(acc[j][1] + bA.y, 0.f);
            h0.z = fmaxf(acc[j][2] + bA.z, 0.f);
            h0.w = fmaxf(acc[j][3] + bA.w, 0.f);
            h1.x = fmaxf(acc[j][4] + bB.x, 0.f);
            h1.y = fmaxf(acc[j][5] + bB.y, 0.f);
            h1.z = fmaxf(acc[j][6] + bB.z, 0.f);
            h1.w = fmaxf(acc[j][7] + bB.w, 0.f);
            *(float4*)&h1s[(ng * 2 + j) * 68 + og * 8 + 0] = h0;
            *(float4*)&h1s[(ng * 2 + j) * 68 + og * 8 + 4] = h1;
        }
    }
    __syncthreads();

    // stage 3: z = h1 @ w2a  -> g_z and g_agg2 = z + b2a
    {
        float acc[2][8] = {};
        #pragma unroll 2
        for (int k4 = 0; k4 < DH; k4 += 4) {
            float4 xa = h1s4[(ng * 2 + 0) * 17 + (k4 >> 2)];
            float4 xb = h1s4[(ng * 2 + 1) * 17 + (k4 >> 2)];
            float xav[4] = {xa.x, xa.y, xa.z, xa.w};
            float xbv[4] = {xb.x, xb.y, xb.z, xb.w};
            #pragma unroll
            for (int kk = 0; kk < 4; kk++) {
                float4 wA = ws2_4[(k4 + kk) * 16 + og * 2 + 0];
                float4 wB = ws2_4[(k4 + kk) * 16 + og * 2 + 1];
                acc[0][0] += xav[kk] * wA.x;  acc[0][1] += xav[kk] * wA.y;
                acc[0][2] += xav[kk] * wA.z;  acc[0][3] += xav[kk] * wA.w;
                acc[0][4] += xav[kk] * wB.x;  acc[0][5] += xav[kk] * wB.y;
                acc[0][6] += xav[kk] * wB.z;  acc[0][7] += xav[kk] * wB.w;
                acc[1][0] += xbv[kk] * wA.x;  acc[1][1] += xbv[kk] * wA.y;
                acc[1][2] += xbv[kk] * wA.z;  acc[1][3] += xbv[kk] * wA.w;
                acc[1][4] += xbv[kk] * wB.x;  acc[1][5] += xbv[kk] * wB.y;
                acc[1][6] += xbv[kk] * wB.z;  acc[1][7] += xbv[kk] * wB.w;
            }
        }
        float4 bA = ((const float4*)b2a)[og * 2 + 0];
        float4 bB = ((const float4*)b2a)[og * 2 + 1];
        #pragma unroll
        for (int j = 0; j < 2; j++) {
            int node = nb + ng * 2 + j;
            if (node < NN) {
                float4 z0 = make_float4(acc[j][0], acc[j][1], acc[j][2], acc[j][3]);
                float4 z1 = make_float4(acc[j][4], acc[j][5], acc[j][6], acc[j][7]);
                size_t g = (size_t)node * 16 + og * 2;
                ((float4*)g_z)[g + 0] = z0;
                ((float4*)g_z)[g + 1] = z1;
                ((float4*)g_agg2)[g + 0] =
                    make_float4(z0.x + bA.x, z0.y + bA.y, z0.z + bA.z, z0.w + bA.w);
                ((float4*)g_agg2)[g + 1] =
                    make_float4(z1.x + bB.x, z1.y + bB.y, z1.z + bB.z, z1.w + bB.w);
            }
        }
    }
}

// ---------------------------------------------------------------------------
// Reduce: sums = sum_nodes relu(agg2)
// ---------------------------------------------------------------------------
__global__ void reduce_kernel() {
    __shared__ float sd[256];
    const int t = threadIdx.x;
    const int ch = t & 63;
    const int ns = t >> 6;   // 0..3
    float acc = 0.f;
    for (int node = blockIdx.x * 4 + ns; node < NN; node += gridDim.x * 4) {
        float v = g_agg2[(size_t)node * 64 + ch];
        acc += fmaxf(v, 0.f);
    }
    sd[t] = acc;
    __syncthreads();
    if (t < 64)
        atomicAdd(&g_sums[ch], sd[t] + sd[t + 64] + sd[t + 128] + sd[t + 192]);
}

// ---------------------------------------------------------------------------
// Final: out = sums @ w2b + NN * b2b    (1 x 64)
// ---------------------------------------------------------------------------
__global__ void final_kernel(const float* __restrict__ w2b,
                             const float* __restrict__ b2b,
                             float* __restrict__ out) {
    int o = threadIdx.x;
    float acc = (float)NN * b2b[o];
    #pragma unroll 8
    for (int j = 0; j < 64; j++)
        acc += g_sums[j] * w2b[j * 64 + o];
    out[o] = acc;
}

// ---------------------------------------------------------------------------
extern "C" void kernel_launch(void* const* d_in, const int* in_sizes, int n_in,
                              void* d_out, int out_size) {
    const float* x   = (const float*)d_in[0];
    const int*   ei  = (const int*)d_in[1];   // int32
    const float* w1a = (const float*)d_in[2];
    const float* b1a = (const float*)d_in[3];
    const float* w1b = (const float*)d_in[4];
    const float* b1b = (const float*)d_in[5];
    const float* w2a = (const float*)d_in[6];
    const float* b2a = (const float*)d_in[7];
    const float* w2b = (const float*)d_in[8];
    const float* b2b = (const float*)d_in[9];
    float*       out = (float*)d_out;

    (void)in_sizes; (void)n_in; (void)out_size;

    const int SMEM_G1  = (DIN * DH + 64 * 132) * 4;           // 66560 B
    const int SMEM_MID = (2 * DH * DH + 2 * 64 * 68) * 4;     // 67584 B
    cudaFuncSetAttribute(gemm1_kernel,
                         cudaFuncAttributeMaxDynamicSharedMemorySize, SMEM_G1);
    cudaFuncSetAttribute(fused_mid_kernel,
                         cudaFuncAttributeMaxDynamicSharedMemorySize, SMEM_MID);

    gemm1_kernel<<<(NN + 63) / 64, 256, SMEM_G1>>>(x, w1a, b1a);
    scatter1_kernel<<<(int)(((long long)NE * 16 + 255) / 256), 256>>>(ei);
    fused_mid_kernel<<<(NN + 63) / 64, 256, SMEM_MID>>>(w1b, b1b, w2a, b2a);
    scatter2_kernel<<<(int)(((long long)NE * 16 + 255) / 256), 256>>>(ei);
    reduce_kernel<<<1184, 256>>>();
    final_kernel<<<1, 64>>>(w2b, b2b, out);
}

// round 5
// speedup vs baseline: 1.2461x; 1.2269x over previous
#include <cuda_runtime.h>

#define NN 100000
#define NE 1600000
#define DIN 128
#define DH  64
#define NB_SCAN 25   // ceil(NN / 4096)

// Scratch (static device globals — no allocation allowed)
__device__ __align__(16) float g_y[NN * DH];    // x @ w1a
__device__ __align__(16) float g_t1[NN * DH];   // relu(y + b1a + sum_{j->i} y[j])
__device__ __align__(16) float g_z[NN * DH];    // h1 @ w2a
__device__ __align__(16) float g_sums[DH];      // pooled sums
__device__ int g_deg[NN];
__device__ int g_rowptr[NN + 1];
__device__ int g_cursor[NN];
__device__ int g_csr_src[NE];
__device__ int g_bsum[NB_SCAN];
__device__ int g_boff[NB_SCAN];

// ---------------------------------------------------------------------------
// f32x2 packed-FMA helpers (Blackwell dual-pipe fp32)
// ---------------------------------------------------------------------------
__device__ __forceinline__ unsigned long long pack2(float x) {
    unsigned long long r;
    asm("mov.b64 %0, {%1, %1};" : "=l"(r) : "f"(x));
    return r;
}
__device__ __forceinline__ void fma2(unsigned long long& d,
                                     unsigned long long a,
                                     unsigned long long b) {
    asm("fma.rn.f32x2 %0, %1, %2, %0;" : "+l"(d) : "l"(a), "l"(b));
}
__device__ __forceinline__ float2 unpack2(unsigned long long v) {
    float2 f;
    asm("mov.b64 {%0, %1}, %2;" : "=f"(f.x), "=f"(f.y) : "l"(v));
    return f;
}

// ---------------------------------------------------------------------------
// CSR build: zero -> histogram -> block scan -> top scan -> add -> fill
// ---------------------------------------------------------------------------
__global__ void zero0_kernel() {
    int i = blockIdx.x * blockDim.x + threadIdx.x;
    if (i < NN) g_deg[i] = 0;
    if (i < DH) g_sums[i] = 0.f;
}

__global__ void hist_kernel(const int* __restrict__ ei) {
    int e = blockIdx.x * blockDim.x + threadIdx.x;
    if (e >= NE) return;
    unsigned dst = (unsigned)ei[NE + e];
    if (dst < NN) atomicAdd(&g_deg[dst], 1);
}

__global__ void scan_blocks_kernel() {
    __shared__ int warp_sums[32];
    const int tid = threadIdx.x, blk = blockIdx.x;
    const int base = blk * 4096 + tid * 4;
    int v0 = (base + 0 < NN) ? g_deg[base + 0] : 0;
    int v1 = (base + 1 < NN) ? g_deg[base + 1] : 0;
    int v2 = (base + 2 < NN) ? g_deg[base + 2] : 0;
    int v3 = (base + 3 < NN) ? g_deg[base + 3] : 0;
    int s = v0 + v1 + v2 + v3;
    const int lane = tid & 31, wid = tid >> 5;
    int inc = s;
    #pragma unroll
    for (int o = 1; o < 32; o <<= 1) {
        int n = __shfl_up_sync(0xffffffffu, inc, o);
        if (lane >= o) inc += n;
    }
    if (lane == 31) warp_sums[wid] = inc;
    __syncthreads();
    if (wid == 0) {
        int ws = warp_sums[lane];
        int winc = ws;
        #pragma unroll
        for (int o = 1; o < 32; o <<= 1) {
            int n = __shfl_up_sync(0xffffffffu, winc, o);
            if (lane >= o) winc += n;
        }
        warp_sums[lane] = winc - ws;   // exclusive
        if (lane == 31) g_bsum[blk] = winc;  // block total
    }
    __syncthreads();
    int excl = inc - s + warp_sums[wid];
    if (base + 0 < NN) g_rowptr[base + 0] = excl;           excl += v0;
    if (base + 1 < NN) g_rowptr[base + 1] = excl;           excl += v1;
    if (base + 2 < NN) g_rowptr[base + 2] = excl;           excl += v2;
    if (base + 3 < NN) g_rowptr[base + 3] = excl;
}

__global__ void scan_top_kernel() {
    const int lane = threadIdx.x;
    int s = (lane < NB_SCAN) ? g_bsum[lane] : 0;
    int inc = s;
    #pragma unroll
    for (int o = 1; o < 32; o <<= 1) {
        int n = __shfl_up_sync(0xffffffffu, inc, o);
        if (lane >= o) inc += n;
    }
    if (lane < NB_SCAN) g_boff[lane] = inc - s;
    if (lane == 31) g_rowptr[NN] = inc;
}

__global__ void scan_add_kernel() {
    int i = blockIdx.x * blockDim.x + threadIdx.x;
    if (i >= NN) return;
    int r = g_rowptr[i] + g_boff[i >> 12];
    g_rowptr[i] = r;
    g_cursor[i] = r;
}

__global__ void fill_kernel(const int* __restrict__ ei) {
    int e = blockIdx.x * blockDim.x + threadIdx.x;
    if (e >= NE) return;
    unsigned src = (unsigned)ei[e];
    unsigned dst = (unsigned)ei[NE + e];
    if (src >= NN || dst >= NN) return;
    int pos = atomicAdd(&g_cursor[dst], 1);
    g_csr_src[pos] = (int)src;
}

// ---------------------------------------------------------------------------
// GEMM1: y = x @ w1a      [100000,128] x [128,64]   (f32x2 packed FMA)
// 64 nodes/block, 256 threads; thread = 2 nodes x 8 outs.
// ---------------------------------------------------------------------------
__global__ void gemm1_kernel(const float* __restrict__ x,
                             const float* __restrict__ w1a) {
    extern __shared__ float sm[];
    float* ws = sm;                 // 128*64
    float* xs = sm + DIN * DH;      // 64 rows, stride 132 floats (33 float4)

    const int t = threadIdx.x;
    const int nb = blockIdx.x * 64;

    #pragma unroll
    for (int i = 0; i < (DIN * DH) / 256; i++)
        ws[i * 256 + t] = w1a[i * 256 + t];

    #pragma unroll
    for (int i = 0; i < 8; i++) {
        int flat = i * 256 + t;     // float4 index
        int node = flat >> 5;
        int f4   = flat & 31;
        float4 v = make_float4(0.f, 0.f, 0.f, 0.f);
        if (nb + node < NN)
            v = ((const float4*)x)[(size_t)(nb + node) * 32 + f4];
        *(float4*)&xs[node * 132 + f4 * 4] = v;
    }
    __syncthreads();

    const int og = t & 7;     // outs og*8 .. og*8+7
    const int ng = t >> 3;    // nodes ng*2, ng*2+1
    const ulonglong2* wsu = (const ulonglong2*)ws;   // 16 ull2 per row of 64
    const float4* xs4 = (const float4*)xs;

    unsigned long long acc[2][4] = {};
    #pragma unroll 2
    for (int k4 = 0; k4 < DIN; k4 += 4) {
        float4 xa = xs4[(ng * 2 + 0) * 33 + (k4 >> 2)];
        float4 xb = xs4[(ng * 2 + 1) * 33 + (k4 >> 2)];
        float xav[4] = {xa.x, xa.y, xa.z, xa.w};
        float xbv[4] = {xb.x, xb.y, xb.z, xb.w};
        #pragma unroll
        for (int kk = 0; kk < 4; kk++) {
            unsigned long long a2 = pack2(xav[kk]);
            unsigned long long b2 = pack2(xbv[kk]);
            ulonglong2 wA = wsu[(k4 + kk) * 16 + og * 2 + 0];
            ulonglong2 wB = wsu[(k4 + kk) * 16 + og * 2 + 1];
            fma2(acc[0][0], a2, wA.x); fma2(acc[0][1], a2, wA.y);
            fma2(acc[0][2], a2, wB.x); fma2(acc[0][3], a2, wB.y);
            fma2(acc[1][0], b2, wA.x); fma2(acc[1][1], b2, wA.y);
            fma2(acc[1][2], b2, wB.x); fma2(acc[1][3], b2, wB.y);
        }
    }
    #pragma unroll
    for (int j = 0; j < 2; j++) {
        int node = nb + ng * 2 + j;
        if (node < NN) {
            float2 p0 = unpack2(acc[j][0]);
            float2 p1 = unpack2(acc[j][1]);
            float2 p2 = unpack2(acc[j][2]);
            float2 p3 = unpack2(acc[j][3]);
            size_t g = (size_t)node * 16 + og * 2;
            ((float4*)g_y)[g + 0] = make_float4(p0.x, p0.y, p1.x, p1.y);
            ((float4*)g_y)[g + 1] = make_float4(p2.x, p2.y, p3.x, p3.y);
        }
    }
}

// ---------------------------------------------------------------------------
// Gather1: t1[i] = relu(y[i] + b1a + sum_{j->i} y[j])
// 16 nodes/block x 16 threads/node; edge loop 4-way unrolled (MLP=4).
// ---------------------------------------------------------------------------
__global__ void gather1_kernel(const float* __restrict__ b1a) {
    const int t = threadIdx.x;
    const int node = blockIdx.x * 16 + (t >> 4);
    const int c = t & 15;
    if (node >= NN) return;
    const int beg = g_rowptr[node];
    const int end = g_rowptr[node + 1];
    float4 acc = ((const float4*)g_y)[(size_t)node * 16 + c];
    float4 bb = ((const float4*)b1a)[c];
    acc.x += bb.x; acc.y += bb.y; acc.z += bb.z; acc.w += bb.w;
    int e = beg;
    for (; e + 4 <= end; e += 4) {
        int s0 = __ldg(&g_csr_src[e + 0]);
        int s1 = __ldg(&g_csr_src[e + 1]);
        int s2 = __ldg(&g_csr_src[e + 2]);
        int s3 = __ldg(&g_csr_src[e + 3]);
        float4 v0 = ((const float4*)g_y)[(size_t)s0 * 16 + c];
        float4 v1 = ((const float4*)g_y)[(size_t)s1 * 16 + c];
        float4 v2 = ((const float4*)g_y)[(size_t)s2 * 16 + c];
        float4 v3 = ((const float4*)g_y)[(size_t)s3 * 16 + c];
        acc.x += (v0.x + v1.x) + (v2.x + v3.x);
        acc.y += (v0.y + v1.y) + (v2.y + v3.y);
        acc.z += (v0.z + v1.z) + (v2.z + v3.z);
        acc.w += (v0.w + v1.w) + (v2.w + v3.w);
    }
    for (; e < end; e++) {
        int s = __ldg(&g_csr_src[e]);
        float4 v = ((const float4*)g_y)[(size_t)s * 16 + c];
        acc.x += v.x; acc.y += v.y; acc.z += v.z; acc.w += v.w;
    }
    acc.x = fmaxf(acc.x, 0.f); acc.y = fmaxf(acc.y, 0.f);
    acc.z = fmaxf(acc.z, 0.f); acc.w = fmaxf(acc.w, 0.f);
    ((float4*)g_t1)[(size_t)node * 16 + c] = acc;
}

// ---------------------------------------------------------------------------
// Fused middle:
//   h1 = relu(t1 @ w1b + b1b)   (smem)
//   z  = h1 @ w2a               (-> g_z; b2a applied in gather2)
// 64 nodes/block, 256 threads; thread = 2 nodes x 8 outs; f32x2 FMA.
// ---------------------------------------------------------------------------
__global__ void fused_mid_kernel(const float* __restrict__ w1b,
                                 const float* __restrict__ b1b,
                                 const float* __restrict__ w2a) {
    extern __shared__ float sm[];
    float* ws1 = sm;                   // 64*64
    float* ws2 = sm + 4096;            // 64*64
    float* t1s = sm + 8192;            // 64 x stride 68
    float* h1s = t1s + 64 * 68;        // 64 x stride 68
    __shared__ __align__(16) float b1bs[64];

    const int t = threadIdx.x;
    const int nb = blockIdx.x * 64;

    #pragma unroll
    for (int i = 0; i < 16; i++) {
        ws1[i * 256 + t] = w1b[i * 256 + t];
        ws2[i * 256 + t] = w2a[i * 256 + t];
    }
    if (t < 64) b1bs[t] = b1b[t];

    #pragma unroll
    for (int i = 0; i < 4; i++) {
        int flat = i * 256 + t;   // float4 index in 64x16
        int node = flat >> 4;
        int f4   = flat & 15;
        float4 v = make_float4(0.f, 0.f, 0.f, 0.f);
        if (nb + node < NN)
            v = ((const float4*)g_t1)[(size_t)(nb + node) * 16 + f4];
        *(float4*)&t1s[node * 68 + f4 * 4] = v;
    }
    __syncthreads();

    const int og = t & 7;
    const int ng = t >> 3;
    const ulonglong2* ws1u = (const ulonglong2*)ws1;
    const ulonglong2* ws2u = (const ulonglong2*)ws2;
    const float4* t1s4 = (const float4*)t1s;
    const float4* h1s4 = (const float4*)h1s;

    // stage 2: h1 = relu(t1 @ w1b + b1b)
    {
        unsigned long long acc[2][4] = {};
        #pragma unroll 2
        for (int k4 = 0; k4 < DH; k4 += 4) {
            float4 xa = t1s4[(ng * 2 + 0) * 17 + (k4 >> 2)];
            float4 xb = t1s4[(ng * 2 + 1) * 17 + (k4 >> 2)];
            float xav[4] = {xa.x, xa.y, xa.z, xa.w};
            float xbv[4] = {xb.x, xb.y, xb.z, xb.w};
            #pragma unroll
            for (int kk = 0; kk < 4; kk++) {
                unsigned long long a2 = pack2(xav[kk]);
                unsigned long long b2 = pack2(xbv[kk]);
                ulonglong2 wA = ws1u[(k4 + kk) * 16 + og * 2 + 0];
                ulonglong2 wB = ws1u[(k4 + kk) * 16 + og * 2 + 1];
                fma2(acc[0][0], a2, wA.x); fma2(acc[0][1], a2, wA.y);
                fma2(acc[0][2], a2, wB.x); fma2(acc[0][3], a2, wB.y);
                fma2(acc[1][0], b2, wA.x); fma2(acc[1][1], b2, wA.y);
                fma2(acc[1][2], b2, wB.x); fma2(acc[1][3], b2, wB.y);
            }
        }
        float4 bA = *(const float4*)&b1bs[og * 8 + 0];
        float4 bB = *(const float4*)&b1bs[og * 8 + 4];
        #pragma unroll
        for (int j = 0; j < 2; j++) {
            float2 p0 = unpack2(acc[j][0]);
            float2 p1 = unpack2(acc[j][1]);
            float2 p2 = unpack2(acc[j][2]);
            float2 p3 = unpack2(acc[j][3]);
            float4 h0, h1;
            h0.x = fmaxf(p0.x + bA.x, 0.f);
            h0.y = fmaxf(p0.y + bA.y, 0.f);
            h0.z = fmaxf(p1.x + bA.z, 0.f);
            h0.w = fmaxf(p1.y + bA.w, 0.f);
            h1.x = fmaxf(p2.x + bB.x, 0.f);
            h1.y = fmaxf(p2.y + bB.y, 0.f);
            h1.z = fmaxf(p3.x + bB.z, 0.f);
            h1.w = fmaxf(p3.y + bB.w, 0.f);
            *(float4*)&h1s[(ng * 2 + j) * 68 + og * 8 + 0] = h0;
            *(float4*)&h1s[(ng * 2 + j) * 68 + og * 8 + 4] = h1;
        }
    }
    __syncthreads();

    // stage 3: z = h1 @ w2a -> g_z
    {
        unsigned long long acc[2][4] = {};
        #pragma unroll 2
        for (int k4 = 0; k4 < DH; k4 += 4) {
            float4 xa = h1s4[(ng * 2 + 0) * 17 + (k4 >> 2)];
            float4 xb = h1s4[(ng * 2 + 1) * 17 + (k4 >> 2)];
            float xav[4] = {xa.x, xa.y, xa.z, xa.w};
            float xbv[4] = {xb.x, xb.y, xb.z, xb.w};
            #pragma unroll
            for (int kk = 0; kk < 4; kk++) {
                unsigned long long a2 = pack2(xav[kk]);
                unsigned long long b2 = pack2(xbv[kk]);
                ulonglong2 wA = ws2u[(k4 + kk) * 16 + og * 2 + 0];
                ulonglong2 wB = ws2u[(k4 + kk) * 16 + og * 2 + 1];
                fma2(acc[0][0], a2, wA.x); fma2(acc[0][1], a2, wA.y);
                fma2(acc[0][2], a2, wB.x); fma2(acc[0][3], a2, wB.y);
                fma2(acc[1][0], b2, wA.x); fma2(acc[1][1], b2, wA.y);
                fma2(acc[1][2], b2, wB.x); fma2(acc[1][3], b2, wB.y);
            }
        }
        #pragma unroll
        for (int j = 0; j < 2; j++) {
            int node = nb + ng * 2 + j;
            if (node < NN) {
                float2 p0 = unpack2(acc[j][0]);
                float2 p1 = unpack2(acc[j][1]);
                float2 p2 = unpack2(acc[j][2]);
                float2 p3 = unpack2(acc[j][3]);
                size_t g = (size_t)node * 16 + og * 2;
                ((float4*)g_z)[g + 0] = make_float4(p0.x, p0.y, p1.x, p1.y);
                ((float4*)g_z)[g + 1] = make_float4(p2.x, p2.y, p3.x, p3.y);
            }
        }
    }
}

// ---------------------------------------------------------------------------
// Gather2 + pool: sums += relu(z[i] + b2a + sum_{j->i} z[j]) over all i
// grid-strided; one block-level reduction + 64 atomics per block.
// ---------------------------------------------------------------------------
__global__ void gather2_kernel(const float* __restrict__ b2a) {
    __shared__ __align__(16) float4 sd[256];
    const int t = threadIdx.x;
    const int c = t & 15;
    const int slot = t >> 4;
    float4 bb = ((const float4*)b2a)[c];
    float4 pool = make_float4(0.f, 0.f, 0.f, 0.f);

    for (int node = blockIdx.x * 16 + slot; node < NN; node += gridDim.x * 16) {
        const int beg = g_rowptr[node];
        const int end = g_rowptr[node + 1];
        float4 acc = ((const float4*)g_z)[(size_t)node * 16 + c];
        acc.x += bb.x; acc.y += bb.y; acc.z += bb.z; acc.w += bb.w;
        int e = beg;
        for (; e + 4 <= end; e += 4) {
            int s0 = __ldg(&g_csr_src[e + 0]);
            int s1 = __ldg(&g_csr_src[e + 1]);
            int s2 = __ldg(&g_csr_src[e + 2]);
            int s3 = __ldg(&g_csr_src[e + 3]);
            float4 v0 = ((const float4*)g_z)[(size_t)s0 * 16 + c];
            float4 v1 = ((const float4*)g_z)[(size_t)s1 * 16 + c];
            float4 v2 = ((const float4*)g_z)[(size_t)s2 * 16 + c];
            float4 v3 = ((const float4*)g_z)[(size_t)s3 * 16 + c];
            acc.x += (v0.x + v1.x) + (v2.x + v3.x);
            acc.y += (v0.y + v1.y) + (v2.y + v3.y);
            acc.z += (v0.z + v1.z) + (v2.z + v3.z);
            acc.w += (v0.w + v1.w) + (v2.w + v3.w);
        }
        for (; e < end; e++) {
            int s = __ldg(&g_csr_src[e]);
            float4 v = ((const float4*)g_z)[(size_t)s * 16 + c];
            acc.x += v.x; acc.y += v.y; acc.z += v.z; acc.w += v.w;
        }
        pool.x += fmaxf(acc.x, 0.f);
        pool.y += fmaxf(acc.y, 0.f);
        pool.z += fmaxf(acc.z, 0.f);
        pool.w += fmaxf(acc.w, 0.f);
    }
    sd[t] = pool;
    __syncthreads();
    if (t < 16) {
        float4 s = sd[t];
        #pragma unroll
        for (int i = 1; i < 16; i++) {
            float4 v = sd[t + i * 16];
            s.x += v.x; s.y += v.y; s.z += v.z; s.w += v.w;
        }
        atomicAdd(&g_sums[t * 4 + 0], s.x);
        atomicAdd(&g_sums[t * 4 + 1], s.y);
        atomicAdd(&g_sums[t * 4 + 2], s.z);
        atomicAdd(&g_sums[t * 4 + 3], s.w);
    }
}

// ---------------------------------------------------------------------------
// Final: out = sums @ w2b + NN * b2b    (1 x 64)
// ---------------------------------------------------------------------------
__global__ void final_kernel(const float* __restrict__ w2b,
                             const float* __restrict__ b2b,
                             float* __restrict__ out) {
    int o = threadIdx.x;
    float acc = (float)NN * b2b[o];
    #pragma unroll 8
    for (int j = 0; j < 64; j++)
        acc += g_sums[j] * w2b[j * 64 + o];
    out[o] = acc;
}

// ---------------------------------------------------------------------------
extern "C" void kernel_launch(void* const* d_in, const int* in_sizes, int n_in,
                              void* d_out, int out_size) {
    const float* x   = (const float*)d_in[0];
    const int*   ei  = (const int*)d_in[1];   // int32
    const float* w1a = (const float*)d_in[2];
    const float* b1a = (const float*)d_in[3];
    const float* w1b = (const float*)d_in[4];
    const float* b1b = (const float*)d_in[5];
    const float* w2a = (const float*)d_in[6];
    const float* b2a = (const float*)d_in[7];
    const float* w2b = (const float*)d_in[8];
    const float* b2b = (const float*)d_in[9];
    float*       out = (float*)d_out;

    (void)in_sizes; (void)n_in; (void)out_size;

    const int SMEM_G1  = (DIN * DH + 64 * 132) * 4;           // 66560 B
    const int SMEM_MID = (2 * DH * DH + 2 * 64 * 68) * 4;     // 67584 B
    cudaFuncSetAttribute(gemm1_kernel,
                         cudaFuncAttributeMaxDynamicSharedMemorySize, SMEM_G1);
    cudaFuncSetAttribute(fused_mid_kernel,
                         cudaFuncAttributeMaxDynamicSharedMemorySize, SMEM_MID);

    // CSR build
    zero0_kernel<<<(NN + 255) / 256, 256>>>();
    hist_kernel<<<(NE + 255) / 256, 256>>>(ei);
    scan_blocks_kernel<<<NB_SCAN, 1024>>>();
    scan_top_kernel<<<1, 32>>>();
    scan_add_kernel<<<(NN + 255) / 256, 256>>>();
    fill_kernel<<<(NE + 255) / 256, 256>>>(ei);

    // Compute
    gemm1_kernel<<<(NN + 63) / 64, 256, SMEM_G1>>>(x, w1a);
    gather1_kernel<<<(NN + 15) / 16, 256>>>(b1a);
    fused_mid_kernel<<<(NN + 63) / 64, 256, SMEM_MID>>>(w1b, b1b, w2a);
    gather2_kernel<<<1184, 256>>>(b2a);
    final_kernel<<<1, 64>>>(w2b, b2b, out);
}

// round 6
// speedup vs baseline: 1.2868x; 1.0327x over previous
#include <cuda_runtime.h>

#define NN 100000
#define NE 1600000
#define DIN 128
#define DH  64
#define NB_SCAN 25   // ceil(NN / 4096)

// Scratch (static device globals — no allocation allowed)
__device__ __align__(16) float g_y[NN * DH];    // x @ w1a
__device__ __align__(16) float g_z[NN * DH];    // h1 @ w2a
__device__ __align__(16) float g_sums[DH];      // pooled sums
__device__ int g_deg[NN];
__device__ int g_rowptr[NN + 1];
__device__ int g_cursor[NN];
__device__ int g_csr_src[NE];
__device__ int g_bsum[NB_SCAN];
__device__ int g_boff[NB_SCAN];

// ---------------------------------------------------------------------------
// f32x2 packed-FMA helpers (Blackwell dual-pipe fp32)
// ---------------------------------------------------------------------------
__device__ __forceinline__ unsigned long long pack2(float x) {
    unsigned long long r;
    asm("mov.b64 %0, {%1, %1};" : "=l"(r) : "f"(x));
    return r;
}
__device__ __forceinline__ void fma2(unsigned long long& d,
                                     unsigned long long a,
                                     unsigned long long b) {
    asm("fma.rn.f32x2 %0, %1, %2, %0;" : "+l"(d) : "l"(a), "l"(b));
}
__device__ __forceinline__ float2 unpack2(unsigned long long v) {
    float2 f;
    asm("mov.b64 {%0, %1}, %2;" : "=f"(f.x), "=f"(f.y) : "l"(v));
    return f;
}

// ---------------------------------------------------------------------------
// CSR build: zero -> histogram -> block scan -> top scan -> add -> fill
// ---------------------------------------------------------------------------
__global__ void zero0_kernel() {
    int i = blockIdx.x * blockDim.x + threadIdx.x;
    if (i < NN) g_deg[i] = 0;
    if (i < DH) g_sums[i] = 0.f;
}

__global__ void hist_kernel(const int* __restrict__ ei) {
    int e = blockIdx.x * blockDim.x + threadIdx.x;
    if (e >= NE) return;
    unsigned dst = (unsigned)ei[NE + e];
    if (dst < NN) atomicAdd(&g_deg[dst], 1);
}

__global__ void scan_blocks_kernel() {
    __shared__ int warp_sums[32];
    const int tid = threadIdx.x, blk = blockIdx.x;
    const int base = blk * 4096 + tid * 4;
    int v0 = (base + 0 < NN) ? g_deg[base + 0] : 0;
    int v1 = (base + 1 < NN) ? g_deg[base + 1] : 0;
    int v2 = (base + 2 < NN) ? g_deg[base + 2] : 0;
    int v3 = (base + 3 < NN) ? g_deg[base + 3] : 0;
    int s = v0 + v1 + v2 + v3;
    const int lane = tid & 31, wid = tid >> 5;
    int inc = s;
    #pragma unroll
    for (int o = 1; o < 32; o <<= 1) {
        int n = __shfl_up_sync(0xffffffffu, inc, o);
        if (lane >= o) inc += n;
    }
    if (lane == 31) warp_sums[wid] = inc;
    __syncthreads();
    if (wid == 0) {
        int ws = warp_sums[lane];
        int winc = ws;
        #pragma unroll
        for (int o = 1; o < 32; o <<= 1) {
            int n = __shfl_up_sync(0xffffffffu, winc, o);
            if (lane >= o) winc += n;
        }
        warp_sums[lane] = winc - ws;   // exclusive
        if (lane == 31) g_bsum[blk] = winc;  // block total
    }
    __syncthreads();
    int excl = inc - s + warp_sums[wid];
    if (base + 0 < NN) g_rowptr[base + 0] = excl;           excl += v0;
    if (base + 1 < NN) g_rowptr[base + 1] = excl;           excl += v1;
    if (base + 2 < NN) g_rowptr[base + 2] = excl;           excl += v2;
    if (base + 3 < NN) g_rowptr[base + 3] = excl;
}

__global__ void scan_top_kernel() {
    const int lane = threadIdx.x;
    int s = (lane < NB_SCAN) ? g_bsum[lane] : 0;
    int inc = s;
    #pragma unroll
    for (int o = 1; o < 32; o <<= 1) {
        int n = __shfl_up_sync(0xffffffffu, inc, o);
        if (lane >= o) inc += n;
    }
    if (lane < NB_SCAN) g_boff[lane] = inc - s;
    if (lane == 31) g_rowptr[NN] = inc;
}

__global__ void scan_add_kernel() {
    int i = blockIdx.x * blockDim.x + threadIdx.x;
    if (i >= NN) return;
    int r = g_rowptr[i] + g_boff[i >> 12];
    g_rowptr[i] = r;
    g_cursor[i] = r;
}

__global__ void fill_kernel(const int* __restrict__ ei) {
    int e = blockIdx.x * blockDim.x + threadIdx.x;
    if (e >= NE) return;
    unsigned src = (unsigned)ei[e];
    unsigned dst = (unsigned)ei[NE + e];
    if (src >= NN || dst >= NN) return;
    int pos = atomicAdd(&g_cursor[dst], 1);
    g_csr_src[pos] = (int)src;
}

// ---------------------------------------------------------------------------
// CSR gather core: acc += sum_{e in [beg,end)} vec[csr_src[e]][c]  (float4 lane c)
// 8-deep unrolled for MLP.
// ---------------------------------------------------------------------------
__device__ __forceinline__ float4 gather_row(const float* __restrict__ vec,
                                             int beg, int end, int c,
                                             float4 acc) {
    const float4* v4 = (const float4*)vec;
    int e = beg;
    for (; e + 8 <= end; e += 8) {
        int s0 = __ldg(&g_csr_src[e + 0]);
        int s1 = __ldg(&g_csr_src[e + 1]);
        int s2 = __ldg(&g_csr_src[e + 2]);
        int s3 = __ldg(&g_csr_src[e + 3]);
        int s4 = __ldg(&g_csr_src[e + 4]);
        int s5 = __ldg(&g_csr_src[e + 5]);
        int s6 = __ldg(&g_csr_src[e + 6]);
        int s7 = __ldg(&g_csr_src[e + 7]);
        float4 v0 = v4[(size_t)s0 * 16 + c];
        float4 v1 = v4[(size_t)s1 * 16 + c];
        float4 v2 = v4[(size_t)s2 * 16 + c];
        float4 v3 = v4[(size_t)s3 * 16 + c];
        float4 v5 = v4[(size_t)s4 * 16 + c];
        float4 v6 = v4[(size_t)s5 * 16 + c];
        float4 v7 = v4[(size_t)s6 * 16 + c];
        float4 v8 = v4[(size_t)s7 * 16 + c];
        acc.x += ((v0.x + v1.x) + (v2.x + v3.x)) + ((v5.x + v6.x) + (v7.x + v8.x));
        acc.y += ((v0.y + v1.y) + (v2.y + v3.y)) + ((v5.y + v6.y) + (v7.y + v8.y));
        acc.z += ((v0.z + v1.z) + (v2.z + v3.z)) + ((v5.z + v6.z) + (v7.z + v8.z));
        acc.w += ((v0.w + v1.w) + (v2.w + v3.w)) + ((v5.w + v6.w) + (v7.w + v8.w));
    }
    for (; e + 4 <= end; e += 4) {
        int s0 = __ldg(&g_csr_src[e + 0]);
        int s1 = __ldg(&g_csr_src[e + 1]);
        int s2 = __ldg(&g_csr_src[e + 2]);
        int s3 = __ldg(&g_csr_src[e + 3]);
        float4 v0 = v4[(size_t)s0 * 16 + c];
        float4 v1 = v4[(size_t)s1 * 16 + c];
        float4 v2 = v4[(size_t)s2 * 16 + c];
        float4 v3 = v4[(size_t)s3 * 16 + c];
        acc.x += (v0.x + v1.x) + (v2.x + v3.x);
        acc.y += (v0.y + v1.y) + (v2.y + v3.y);
        acc.z += (v0.z + v1.z) + (v2.z + v3.z);
        acc.w += (v0.w + v1.w) + (v2.w + v3.w);
    }
    for (; e < end; e++) {
        int s = __ldg(&g_csr_src[e]);
        float4 v = v4[(size_t)s * 16 + c];
        acc.x += v.x; acc.y += v.y; acc.z += v.z; acc.w += v.w;
    }
    return acc;
}

// ---------------------------------------------------------------------------
// GEMM1: y = x @ w1a      [100000,128] x [128,64]   (f32x2 packed FMA)
// 64 nodes/block, 256 threads; thread = 2 nodes x 8 outs.
// ---------------------------------------------------------------------------
__global__ void gemm1_kernel(const float* __restrict__ x,
                             const float* __restrict__ w1a) {
    extern __shared__ float sm[];
    float* ws = sm;                 // 128*64
    float* xs = sm + DIN * DH;      // 64 rows, stride 132 floats (33 float4)

    const int t = threadIdx.x;
    const int nb = blockIdx.x * 64;

    #pragma unroll
    for (int i = 0; i < (DIN * DH) / 256; i++)
        ws[i * 256 + t] = w1a[i * 256 + t];

    #pragma unroll
    for (int i = 0; i < 8; i++) {
        int flat = i * 256 + t;     // float4 index
        int node = flat >> 5;
        int f4   = flat & 31;
        float4 v = make_float4(0.f, 0.f, 0.f, 0.f);
        if (nb + node < NN)
            v = ((const float4*)x)[(size_t)(nb + node) * 32 + f4];
        *(float4*)&xs[node * 132 + f4 * 4] = v;
    }
    __syncthreads();

    const int og = t & 7;     // outs og*8 .. og*8+7
    const int ng = t >> 3;    // nodes ng*2, ng*2+1
    const ulonglong2* wsu = (const ulonglong2*)ws;   // 16 ull2 per row of 64
    const float4* xs4 = (const float4*)xs;

    unsigned long long acc[2][4] = {};
    #pragma unroll 2
    for (int k4 = 0; k4 < DIN; k4 += 4) {
        float4 xa = xs4[(ng * 2 + 0) * 33 + (k4 >> 2)];
        float4 xb = xs4[(ng * 2 + 1) * 33 + (k4 >> 2)];
        float xav[4] = {xa.x, xa.y, xa.z, xa.w};
        float xbv[4] = {xb.x, xb.y, xb.z, xb.w};
        #pragma unroll
        for (int kk = 0; kk < 4; kk++) {
            unsigned long long a2 = pack2(xav[kk]);
            unsigned long long b2 = pack2(xbv[kk]);
            ulonglong2 wA = wsu[(k4 + kk) * 16 + og * 2 + 0];
            ulonglong2 wB = wsu[(k4 + kk) * 16 + og * 2 + 1];
            fma2(acc[0][0], a2, wA.x); fma2(acc[0][1], a2, wA.y);
            fma2(acc[0][2], a2, wB.x); fma2(acc[0][3], a2, wB.y);
            fma2(acc[1][0], b2, wA.x); fma2(acc[1][1], b2, wA.y);
            fma2(acc[1][2], b2, wB.x); fma2(acc[1][3], b2, wB.y);
        }
    }
    #pragma unroll
    for (int j = 0; j < 2; j++) {
        int node = nb + ng * 2 + j;
        if (node < NN) {
            float2 p0 = unpack2(acc[j][0]);
            float2 p1 = unpack2(acc[j][1]);
            float2 p2 = unpack2(acc[j][2]);
            float2 p3 = unpack2(acc[j][3]);
            size_t g = (size_t)node * 16 + og * 2;
            ((float4*)g_y)[g + 0] = make_float4(p0.x, p0.y, p1.x, p1.y);
            ((float4*)g_y)[g + 1] = make_float4(p2.x, p2.y, p3.x, p3.y);
        }
    }
}

// ---------------------------------------------------------------------------
// Fused middle (gather1 + 2 GEMMs):
//   t1 = relu(y[i] + b1a + sum_{j->i} y[j])   (CSR gather -> smem)
//   h1 = relu(t1 @ w1b + b1b)                 (smem)
//   z  = h1 @ w2a                             (-> g_z; b2a applied in gather2)
// 64 nodes/block, 256 threads.
// ---------------------------------------------------------------------------
__global__ void fused_mid_kernel(const float* __restrict__ b1a,
                                 const float* __restrict__ w1b,
                                 const float* __restrict__ b1b,
                                 const float* __restrict__ w2a) {
    extern __shared__ float sm[];
    float* ws1 = sm;                   // 64*64
    float* ws2 = sm + 4096;            // 64*64
    float* t1s = sm + 8192;            // 64 x stride 68
    float* h1s = t1s + 64 * 68;        // 64 x stride 68
    __shared__ __align__(16) float b1bs[64];

    const int t = threadIdx.x;
    const int nb = blockIdx.x * 64;

    #pragma unroll
    for (int i = 0; i < 16; i++) {
        ws1[i * 256 + t] = w1b[i * 256 + t];
        ws2[i * 256 + t] = w2a[i * 256 + t];
    }
    if (t < 64) b1bs[t] = b1b[t];

    // stage 1: CSR gather into t1 smem (16 node-slots x 16 channels)
    {
        const int slot = t >> 4;   // 0..15
        const int c = t & 15;
        float4 bb = ((const float4*)b1a)[c];
        #pragma unroll
        for (int i = 0; i < 4; i++) {
            int ln = i * 16 + slot;
            int node = nb + ln;
            float4 acc = make_float4(0.f, 0.f, 0.f, 0.f);
            if (node < NN) {
                acc = ((const float4*)g_y)[(size_t)node * 16 + c];
                acc.x += bb.x; acc.y += bb.y; acc.z += bb.z; acc.w += bb.w;
                int beg = g_rowptr[node];
                int end = g_rowptr[node + 1];
                acc = gather_row(g_y, beg, end, c, acc);
                acc.x = fmaxf(acc.x, 0.f); acc.y = fmaxf(acc.y, 0.f);
                acc.z = fmaxf(acc.z, 0.f); acc.w = fmaxf(acc.w, 0.f);
            }
            *(float4*)&t1s[ln * 68 + c * 4] = acc;
        }
    }
    __syncthreads();

    const int og = t & 7;
    const int ng = t >> 3;
    const ulonglong2* ws1u = (const ulonglong2*)ws1;
    const ulonglong2* ws2u = (const ulonglong2*)ws2;
    const float4* t1s4 = (const float4*)t1s;
    const float4* h1s4 = (const float4*)h1s;

    // stage 2: h1 = relu(t1 @ w1b + b1b)
    {
        unsigned long long acc[2][4] = {};
        #pragma unroll 2
        for (int k4 = 0; k4 < DH; k4 += 4) {
            float4 xa = t1s4[(ng * 2 + 0) * 17 + (k4 >> 2)];
            float4 xb = t1s4[(ng * 2 + 1) * 17 + (k4 >> 2)];
            float xav[4] = {xa.x, xa.y, xa.z, xa.w};
            float xbv[4] = {xb.x, xb.y, xb.z, xb.w};
            #pragma unroll
            for (int kk = 0; kk < 4; kk++) {
                unsigned long long a2 = pack2(xav[kk]);
                unsigned long long b2 = pack2(xbv[kk]);
                ulonglong2 wA = ws1u[(k4 + kk) * 16 + og * 2 + 0];
                ulonglong2 wB = ws1u[(k4 + kk) * 16 + og * 2 + 1];
                fma2(acc[0][0], a2, wA.x); fma2(acc[0][1], a2, wA.y);
                fma2(acc[0][2], a2, wB.x); fma2(acc[0][3], a2, wB.y);
                fma2(acc[1][0], b2, wA.x); fma2(acc[1][1], b2, wA.y);
                fma2(acc[1][2], b2, wB.x); fma2(acc[1][3], b2, wB.y);
            }
        }
        float4 bA = *(const float4*)&b1bs[og * 8 + 0];
        float4 bB = *(const float4*)&b1bs[og * 8 + 4];
        #pragma unroll
        for (int j = 0; j < 2; j++) {
            float2 p0 = unpack2(acc[j][0]);
            float2 p1 = unpack2(acc[j][1]);
            float2 p2 = unpack2(acc[j][2]);
            float2 p3 = unpack2(acc[j][3]);
            float4 h0, h1;
            h0.x = fmaxf(p0.x + bA.x, 0.f);
            h0.y = fmaxf(p0.y + bA.y, 0.f);
            h0.z = fmaxf(p1.x + bA.z, 0.f);
            h0.w = fmaxf(p1.y + bA.w, 0.f);
            h1.x = fmaxf(p2.x + bB.x, 0.f);
            h1.y = fmaxf(p2.y + bB.y, 0.f);
            h1.z = fmaxf(p3.x + bB.z, 0.f);
            h1.w = fmaxf(p3.y + bB.w, 0.f);
            *(float4*)&h1s[(ng * 2 + j) * 68 + og * 8 + 0] = h0;
            *(float4*)&h1s[(ng * 2 + j) * 68 + og * 8 + 4] = h1;
        }
    }
    __syncthreads();

    // stage 3: z = h1 @ w2a -> g_z
    {
        unsigned long long acc[2][4] = {};
        #pragma unroll 2
        for (int k4 = 0; k4 < DH; k4 += 4) {
            float4 xa = h1s4[(ng * 2 + 0) * 17 + (k4 >> 2)];
            float4 xb = h1s4[(ng * 2 + 1) * 17 + (k4 >> 2)];
            float xav[4] = {xa.x, xa.y, xa.z, xa.w};
            float xbv[4] = {xb.x, xb.y, xb.z, xb.w};
            #pragma unroll
            for (int kk = 0; kk < 4; kk++) {
                unsigned long long a2 = pack2(xav[kk]);
                unsigned long long b2 = pack2(xbv[kk]);
                ulonglong2 wA = ws2u[(k4 + kk) * 16 + og * 2 + 0];
                ulonglong2 wB = ws2u[(k4 + kk) * 16 + og * 2 + 1];
                fma2(acc[0][0], a2, wA.x); fma2(acc[0][1], a2, wA.y);
                fma2(acc[0][2], a2, wB.x); fma2(acc[0][3], a2, wB.y);
                fma2(acc[1][0], b2, wA.x); fma2(acc[1][1], b2, wA.y);
                fma2(acc[1][2], b2, wB.x); fma2(acc[1][3], b2, wB.y);
            }
        }
        #pragma unroll
        for (int j = 0; j < 2; j++) {
            int node = nb + ng * 2 + j;
            if (node < NN) {
                float2 p0 = unpack2(acc[j][0]);
                float2 p1 = unpack2(acc[j][1]);
                float2 p2 = unpack2(acc[j][2]);
                float2 p3 = unpack2(acc[j][3]);
                size_t g = (size_t)node * 16 + og * 2;
                ((float4*)g_z)[g + 0] = make_float4(p0.x, p0.y, p1.x, p1.y);
                ((float4*)g_z)[g + 1] = make_float4(p2.x, p2.y, p3.x, p3.y);
            }
        }
    }
}

// ---------------------------------------------------------------------------
// Gather2 + pool: sums += relu(z[i] + b2a + sum_{j->i} z[j]) over all i
// ---------------------------------------------------------------------------
__global__ void gather2_kernel(const float* __restrict__ b2a) {
    __shared__ __align__(16) float4 sd[256];
    const int t = threadIdx.x;
    const int c = t & 15;
    const int slot = t >> 4;
    float4 bb = ((const float4*)b2a)[c];
    float4 pool = make_float4(0.f, 0.f, 0.f, 0.f);

    for (int node = blockIdx.x * 16 + slot; node < NN; node += gridDim.x * 16) {
        float4 acc = ((const float4*)g_z)[(size_t)node * 16 + c];
        acc.x += bb.x; acc.y += bb.y; acc.z += bb.z; acc.w += bb.w;
        int beg = g_rowptr[node];
        int end = g_rowptr[node + 1];
        acc = gather_row(g_z, beg, end, c, acc);
        pool.x += fmaxf(acc.x, 0.f);
        pool.y += fmaxf(acc.y, 0.f);
        pool.z += fmaxf(acc.z, 0.f);
        pool.w += fmaxf(acc.w, 0.f);
    }
    sd[t] = pool;
    __syncthreads();
    if (t < 16) {
        float4 s = sd[t];
        #pragma unroll
        for (int i = 1; i < 16; i++) {
            float4 v = sd[t + i * 16];
            s.x += v.x; s.y += v.y; s.z += v.z; s.w += v.w;
        }
        atomicAdd(&g_sums[t * 4 + 0], s.x);
        atomicAdd(&g_sums[t * 4 + 1], s.y);
        atomicAdd(&g_sums[t * 4 + 2], s.z);
        atomicAdd(&g_sums[t * 4 + 3], s.w);
    }
}

// ---------------------------------------------------------------------------
// Final: out = sums @ w2b + NN * b2b    (1 x 64)
// ---------------------------------------------------------------------------
__global__ void final_kernel(const float* __restrict__ w2b,
                             const float* __restrict__ b2b,
                             float* __restrict__ out) {
    int o = threadIdx.x;
    float acc = (float)NN * b2b[o];
    #pragma unroll 8
    for (int j = 0; j < 64; j++)
        acc += g_sums[j] * w2b[j * 64 + o];
    out[o] = acc;
}

// ---------------------------------------------------------------------------
extern "C" void kernel_launch(void* const* d_in, const int* in_sizes, int n_in,
                              void* d_out, int out_size) {
    const float* x   = (const float*)d_in[0];
    const int*   ei  = (const int*)d_in[1];   // int32
    const float* w1a = (const float*)d_in[2];
    const float* b1a = (const float*)d_in[3];
    const float* w1b = (const float*)d_in[4];
    const float* b1b = (const float*)d_in[5];
    const float* w2a = (const float*)d_in[6];
    const float* b2a = (const float*)d_in[7];
    const float* w2b = (const float*)d_in[8];
    const float* b2b = (const float*)d_in[9];
    float*       out = (float*)d_out;

    (void)in_sizes; (void)n_in; (void)out_size;

    const int SMEM_G1  = (DIN * DH + 64 * 132) * 4;           // 66560 B
    const int SMEM_MID = (2 * DH * DH + 2 * 64 * 68) * 4;     // 67584 B
    cudaFuncSetAttribute(gemm1_kernel,
                         cudaFuncAttributeMaxDynamicSharedMemorySize, SMEM_G1);
    cudaFuncSetAttribute(fused_mid_kernel,
                         cudaFuncAttributeMaxDynamicSharedMemorySize, SMEM_MID);

    // Persistent side stream + fork/join events (host-side resources only;
    // created once, reused every call — device work identical per call).
    static cudaStream_t s2 = nullptr;
    static cudaEvent_t ev_fork = nullptr, ev_join = nullptr;
    if (s2 == nullptr) {
        cudaStreamCreateWithFlags(&s2, cudaStreamNonBlocking);
        cudaEventCreateWithFlags(&ev_fork, cudaEventDisableTiming);
        cudaEventCreateWithFlags(&ev_join, cudaEventDisableTiming);
    }

    // Fork: CSR build on s2 concurrently with gemm1 on the main stream.
    cudaEventRecord(ev_fork, 0);
    cudaStreamWaitEvent(s2, ev_fork, 0);

    zero0_kernel<<<(NN + 255) / 256, 256, 0, s2>>>();
    hist_kernel<<<(NE + 255) / 256, 256, 0, s2>>>(ei);
    scan_blocks_kernel<<<NB_SCAN, 1024, 0, s2>>>();
    scan_top_kernel<<<1, 32, 0, s2>>>();
    scan_add_kernel<<<(NN + 255) / 256, 256, 0, s2>>>();
    fill_kernel<<<(NE + 255) / 256, 256, 0, s2>>>(ei);
    cudaEventRecord(ev_join, s2);

    gemm1_kernel<<<(NN + 63) / 64, 256, SMEM_G1>>>(x, w1a);

    // Join: everything below needs both g_y and the CSR.
    cudaStreamWaitEvent(0, ev_join, 0);

    fused_mid_kernel<<<(NN + 63) / 64, 256, SMEM_MID>>>(b1a, w1b, b1b, w2a);
    gather2_kernel<<<1184, 256>>>(b2a);
    final_kernel<<<1, 64>>>(w2b, b2b, out);
}